// round 3
// baseline (speedup 1.0000x reference)
#include <cuda_runtime.h>
#include <cstdint>

#define TOKS 7
#define THREADS 128
#define STR 68            // float stride for A / scr tiles (conflict-free float4)

// smem float offsets
#define A_FOFF    0                         // 128 x STR  (tf32 A tile)
#define SCR_FOFF  (128 * STR)               // 128 x STR  (f32 scratch)
#define W2_FOFF   (2 * 128 * STR)           // 64 x STR   (tf32, W2t[n][k] = W2[k][n])
#define W3_FOFF   (W2_FOFF + 64 * STR)      // 32 x STR
#define XS_FOFF   (W3_FOFF + 32 * STR)      // 119 float2 = 238 floats
#define W1_FOFF   (XS_FOFF + 240)           // 128 floats
#define B1_FOFF   (W1_FOFF + 128)           // 64
#define SMEM_FLOATS (B1_FOFF + 64)
#define SMEM_BYTES  (SMEM_FLOATS * 4)

__constant__ int c_cnt[17] = {5,3,3,2,2,4,4,3,3,2,2,3,3,3,3,2,2};
__constant__ int c_nbr[17][5] = {
    {0,1,2,5,6},{1,0,3,0,0},{2,0,4,0,0},{3,1,0,0,0},{4,2,0,0,0},
    {5,0,7,11,0},{6,0,8,12,0},{7,5,9,0,0},{8,6,10,0,0},{9,7,0,0,0},
    {10,8,0,0,0},{11,5,13,0,0},{12,6,14,0,0},{13,11,15,0,0},{14,12,16,0,0},
    {15,13,0,0,0},{16,14,0,0,0}};

__device__ __forceinline__ uint32_t f2tf(float f) {
    uint32_t r; asm("cvt.rna.tf32.f32 %0, %1;" : "=r"(r) : "f"(f)); return r;
}

__device__ __forceinline__ void mma8(float c[4], const uint32_t a[4], const uint32_t b[2]) {
    asm volatile(
        "mma.sync.aligned.m16n8k8.row.col.f32.tf32.tf32.f32 "
        "{%0,%1,%2,%3}, {%4,%5,%6,%7}, {%8,%9}, {%0,%1,%2,%3};"
        : "+f"(c[0]), "+f"(c[1]), "+f"(c[2]), "+f"(c[3])
        : "r"(a[0]), "r"(a[1]), "r"(a[2]), "r"(a[3]), "r"(b[0]), "r"(b[1]));
}

extern __shared__ float sm[];

__global__ void __launch_bounds__(THREADS)
sge_mma(const float* __restrict__ x,
        const float* __restrict__ W1, const float* __restrict__ b1,
        const float* __restrict__ W2, const float* __restrict__ b2,
        const float* __restrict__ W3, const float* __restrict__ b3,
        float* __restrict__ out, int NT, int nstages)
{
    const int tid = threadIdx.x;
    const int warp = tid >> 5, lane = tid & 31;
    const int g = lane >> 2, q = lane & 3;
    const int wrow = warp * 32;

    float* Atile = sm + A_FOFF;          // holds tf32 bit patterns (as float storage)
    float* scr   = sm + SCR_FOFF;
    float* w2t   = sm + W2_FOFF;
    float* w3t   = sm + W3_FOFF;
    float2* xs   = (float2*)(sm + XS_FOFF);
    float* w1s   = sm + W1_FOFF;
    float* b1s   = sm + B1_FOFF;

    // ---- stage weights (tf32-rounded, transposed) ----
    for (int i = tid; i < 64 * 64; i += THREADS) {
        int k = i >> 6, n = i & 63;
        ((uint32_t*)w2t)[n * STR + k] = f2tf(W2[i]);
    }
    for (int i = tid; i < 64 * 32; i += THREADS) {
        int k = i >> 5, n = i & 31;
        ((uint32_t*)w3t)[n * STR + k] = f2tf(W3[i]);
    }
    for (int i = tid; i < 128; i += THREADS) w1s[i] = W1[i];
    for (int i = tid; i < 64;  i += THREADS) b1s[i] = b1[i];

    // ---- pinned per-thread bias fragments ----
    float2 b2p[8], b3p[4];
    #pragma unroll
    for (int nt = 0; nt < 8; nt++) {
        int cb = nt * 8 + 2 * q;
        b2p[nt] = make_float2(b2[cb], b2[cb + 1]);
    }
    #pragma unroll
    for (int nt = 0; nt < 4; nt++) {
        int cb = nt * 8 + 2 * q;
        b3p[nt] = make_float2(b3[cb], b3[cb + 1]);
    }
    __syncthreads();

    for (int s = blockIdx.x; s < nstages; s += gridDim.x) {
        const int tok0 = s * TOKS;
        const int vtok = min(TOKS, NT - tok0);
        const int vrows = vtok * 17;

        // ---- stage x ----
        if (tid < vrows) xs[tid] = ((const float2*)x)[tok0 * 17 + tid];
        __syncthreads();

        // ---- layer 1: h1 = relu((agg x) @ W1 + b1) -> scr ----
        if (tid < vrows) {
            int t = tid / 17, jo = tid - t * 17;
            const float2* xb = xs + t * 17;
            float2 xa = make_float2(0.f, 0.f);
            int cnt = c_cnt[jo];
            #pragma unroll
            for (int i = 0; i < 5; i++) if (i < cnt) {
                float2 v = xb[c_nbr[jo][i]];
                xa.x += v.x; xa.y += v.y;
            }
            const float4* w1a = (const float4*)w1s;         // W1[0][*]
            const float4* w1b = (const float4*)(w1s + 64);  // W1[1][*]
            const float4* b1v = (const float4*)b1s;
            float* sr = scr + tid * STR;
            #pragma unroll
            for (int fc = 0; fc < 16; fc++) {
                float4 wa = w1a[fc], wb = w1b[fc], bb = b1v[fc], h;
                h.x = fmaxf(xa.x * wa.x + xa.y * wb.x + bb.x, 0.f);
                h.y = fmaxf(xa.x * wa.y + xa.y * wb.y + bb.y, 0.f);
                h.z = fmaxf(xa.x * wa.z + xa.y * wb.z + bb.z, 0.f);
                h.w = fmaxf(xa.x * wa.w + xa.y * wb.w + bb.w, 0.f);
                *(float4*)(sr + fc * 4) = h;
            }
        }
        __syncthreads();

        // ---- A1 = agg(h1), tf32 -> A tile ----
        for (int task = tid; task < vrows * 16; task += THREADS) {
            int r = task >> 4, fc = task & 15;
            int t = r / 17, jo = r - t * 17, rb = t * 17;
            int cnt = c_cnt[jo];
            float4 acc = make_float4(0.f, 0.f, 0.f, 0.f);
            #pragma unroll
            for (int i = 0; i < 5; i++) if (i < cnt) {
                float4 v = *(const float4*)(scr + (rb + c_nbr[jo][i]) * STR + fc * 4);
                acc.x += v.x; acc.y += v.y; acc.z += v.z; acc.w += v.w;
            }
            uint4 o;
            o.x = f2tf(acc.x); o.y = f2tf(acc.y); o.z = f2tf(acc.z); o.w = f2tf(acc.w);
            *(uint4*)(Atile + r * STR + fc * 4) = o;
        }
        __syncthreads();

        // ---- GEMM1: C1 = A @ W2t^T  (M=128 N=64 K=64), warps split M ----
        {
            float c[2][8][4];
            #pragma unroll
            for (int mt = 0; mt < 2; mt++)
                #pragma unroll
                for (int nt = 0; nt < 8; nt++)
                    #pragma unroll
                    for (int i = 0; i < 4; i++) c[mt][nt][i] = 0.f;

            const uint32_t* Au = (const uint32_t*)Atile;
            const uint32_t* Bu = (const uint32_t*)w2t;
            #pragma unroll
            for (int ks = 0; ks < 8; ks++) {
                const int k0 = ks * 8;
                uint32_t a[2][4];
                #pragma unroll
                for (int mt = 0; mt < 2; mt++) {
                    int r0 = wrow + mt * 16 + g;
                    a[mt][0] = Au[r0 * STR + k0 + q];
                    a[mt][1] = Au[(r0 + 8) * STR + k0 + q];
                    a[mt][2] = Au[r0 * STR + k0 + q + 4];
                    a[mt][3] = Au[(r0 + 8) * STR + k0 + q + 4];
                }
                #pragma unroll
                for (int nt = 0; nt < 8; nt++) {
                    uint32_t b[2];
                    int n = nt * 8 + g;
                    b[0] = Bu[n * STR + k0 + q];
                    b[1] = Bu[n * STR + k0 + q + 4];
                    mma8(c[0][nt], a[0], b);
                    mma8(c[1][nt], a[1], b);
                }
            }
            // relu(+b2) in-fragment -> scr
            #pragma unroll
            for (int mt = 0; mt < 2; mt++) {
                int r0 = wrow + mt * 16 + g;
                #pragma unroll
                for (int nt = 0; nt < 8; nt++) {
                    int cb = nt * 8 + 2 * q;
                    float2 lo, hi;
                    lo.x = fmaxf(c[mt][nt][0] + b2p[nt].x, 0.f);
                    lo.y = fmaxf(c[mt][nt][1] + b2p[nt].y, 0.f);
                    hi.x = fmaxf(c[mt][nt][2] + b2p[nt].x, 0.f);
                    hi.y = fmaxf(c[mt][nt][3] + b2p[nt].y, 0.f);
                    *(float2*)(scr + r0 * STR + cb) = lo;
                    *(float2*)(scr + (r0 + 8) * STR + cb) = hi;
                }
            }
        }
        __syncthreads();

        // ---- A2 = agg(h2), tf32 -> A tile ----
        for (int task = tid; task < vrows * 16; task += THREADS) {
            int r = task >> 4, fc = task & 15;
            int t = r / 17, jo = r - t * 17, rb = t * 17;
            int cnt = c_cnt[jo];
            float4 acc = make_float4(0.f, 0.f, 0.f, 0.f);
            #pragma unroll
            for (int i = 0; i < 5; i++) if (i < cnt) {
                float4 v = *(const float4*)(scr + (rb + c_nbr[jo][i]) * STR + fc * 4);
                acc.x += v.x; acc.y += v.y; acc.z += v.z; acc.w += v.w;
            }
            uint4 o;
            o.x = f2tf(acc.x); o.y = f2tf(acc.y); o.z = f2tf(acc.z); o.w = f2tf(acc.w);
            *(uint4*)(Atile + r * STR + fc * 4) = o;
        }
        __syncthreads();

        // ---- GEMM2: out = A @ W3t^T + b3  (M=128 N=32 K=64), frags -> gmem ----
        {
            float c[2][4][4];
            #pragma unroll
            for (int mt = 0; mt < 2; mt++)
                #pragma unroll
                for (int nt = 0; nt < 4; nt++)
                    #pragma unroll
                    for (int i = 0; i < 4; i++) c[mt][nt][i] = 0.f;

            const uint32_t* Au = (const uint32_t*)Atile;
            const uint32_t* Bu = (const uint32_t*)w3t;
            #pragma unroll
            for (int ks = 0; ks < 8; ks++) {
                const int k0 = ks * 8;
                uint32_t a[2][4];
                #pragma unroll
                for (int mt = 0; mt < 2; mt++) {
                    int r0 = wrow + mt * 16 + g;
                    a[mt][0] = Au[r0 * STR + k0 + q];
                    a[mt][1] = Au[(r0 + 8) * STR + k0 + q];
                    a[mt][2] = Au[r0 * STR + k0 + q + 4];
                    a[mt][3] = Au[(r0 + 8) * STR + k0 + q + 4];
                }
                #pragma unroll
                for (int nt = 0; nt < 4; nt++) {
                    uint32_t b[2];
                    int n = nt * 8 + g;
                    b[0] = Bu[n * STR + k0 + q];
                    b[1] = Bu[n * STR + k0 + q + 4];
                    mma8(c[0][nt], a[0], b);
                    mma8(c[1][nt], a[1], b);
                }
            }
            float* ob = out + (size_t)tok0 * 17 * 32;
            #pragma unroll
            for (int mt = 0; mt < 2; mt++) {
                int r0 = wrow + mt * 16 + g;
                #pragma unroll
                for (int nt = 0; nt < 4; nt++) {
                    int cb = nt * 8 + 2 * q;
                    if (r0 < vrows) {
                        float2 v = make_float2(c[mt][nt][0] + b3p[nt].x,
                                               c[mt][nt][1] + b3p[nt].y);
                        *(float2*)(ob + r0 * 32 + cb) = v;
                    }
                    if (r0 + 8 < vrows) {
                        float2 v = make_float2(c[mt][nt][2] + b3p[nt].x,
                                               c[mt][nt][3] + b3p[nt].y);
                        *(float2*)(ob + (r0 + 8) * 32 + cb) = v;
                    }
                }
            }
        }
        __syncthreads();
    }
}

extern "C" void kernel_launch(void* const* d_in, const int* in_sizes, int n_in,
                              void* d_out, int out_size) {
    const float* x  = (const float*)d_in[0];
    const float* W1 = (const float*)d_in[1];
    const float* b1 = (const float*)d_in[2];
    const float* W2 = (const float*)d_in[3];
    const float* b2 = (const float*)d_in[4];
    const float* W3 = (const float*)d_in[5];
    const float* b3 = (const float*)d_in[6];
    float* out = (float*)d_out;

    const int NT = in_sizes[0] / (17 * 2);          // 65536 tokens
    const int nstages = (NT + TOKS - 1) / TOKS;     // 9363

    static int attr_done = 0;
    if (!attr_done) {
        cudaFuncSetAttribute(sge_mma, cudaFuncAttributeMaxDynamicSharedMemorySize, SMEM_BYTES);
        attr_done = 1;
    }
    int grid = nstages < 296 ? nstages : 296;
    sge_mma<<<grid, THREADS, SMEM_BYTES>>>(x, W1, b1, W2, b2, W3, b3, out, NT, nstages);
}

// round 5
// speedup vs baseline: 1.3841x; 1.3841x over previous
#include <cuda_runtime.h>
#include <cstdint>

#define TOKS 7
#define THREADS 256
#define STR 68            // float stride for A / scr tiles (conflict-free)

// smem float offsets
#define A_FOFF    0                       // 128 x STR tf32 A tile (8704)
#define SCR_FOFF  (128 * STR)             // 128 x STR f32 scratch (8704)
#define B2F_FOFF  (2 * 128 * STR)         // 8ks x 8nt x 32lane x float2 = 4096 floats
#define B3F_FOFF  (B2F_FOFF + 4096)       // 8ks x 4nt x 32lane x float2 = 2048 floats
#define W1_FOFF   (B3F_FOFF + 2048)       // 128
#define B1_FOFF   (W1_FOFF + 128)         // 64
#define SMEM_FLOATS (B1_FOFF + 64)
#define SMEM_BYTES  (SMEM_FLOATS * 4)     // ~95KB -> 2 CTAs/SM

__constant__ int c_cnt[17] = {5,3,3,2,2,4,4,3,3,2,2,3,3,3,3,2,2};
__constant__ int c_nbr[17][5] = {
    {0,1,2,5,6},{1,0,3,0,0},{2,0,4,0,0},{3,1,0,0,0},{4,2,0,0,0},
    {5,0,7,11,0},{6,0,8,12,0},{7,5,9,0,0},{8,6,10,0,0},{9,7,0,0,0},
    {10,8,0,0,0},{11,5,13,0,0},{12,6,14,0,0},{13,11,15,0,0},{14,12,16,0,0},
    {15,13,0,0,0},{16,14,0,0,0}};

__device__ __forceinline__ uint32_t f2tf(float f) {
    uint32_t r; asm("cvt.rna.tf32.f32 %0, %1;" : "=r"(r) : "f"(f)); return r;
}

__device__ __forceinline__ void mma8(float c[4], const uint32_t a[4], uint32_t b0, uint32_t b1) {
    asm volatile(
        "mma.sync.aligned.m16n8k8.row.col.f32.tf32.tf32.f32 "
        "{%0,%1,%2,%3}, {%4,%5,%6,%7}, {%8,%9}, {%0,%1,%2,%3};"
        : "+f"(c[0]), "+f"(c[1]), "+f"(c[2]), "+f"(c[3])
        : "r"(a[0]), "r"(a[1]), "r"(a[2]), "r"(a[3]), "r"(b0), "r"(b1));
}

extern __shared__ float sm[];

__global__ void __launch_bounds__(THREADS, 2)
sge_mma(const float* __restrict__ x,
        const float* __restrict__ W1, const float* __restrict__ b1,
        const float* __restrict__ W2, const float* __restrict__ b2,
        const float* __restrict__ W3, const float* __restrict__ b3,
        float* __restrict__ out, int NT, int nstages)
{
    const int tid = threadIdx.x;
    const int warp = tid >> 5, lane = tid & 31;
    const int g = lane >> 2, q = lane & 3;
    const int r0 = warp * 16 + g;            // this thread's MMA row (and r0+8)

    float* Atile = sm + A_FOFF;              // tf32 bit patterns
    float* scr   = sm + SCR_FOFF;
    uint2* B2f   = (uint2*)(sm + B2F_FOFF);
    uint2* B3f   = (uint2*)(sm + B3F_FOFF);
    float* w1s   = sm + W1_FOFF;
    float* b1s   = sm + B1_FOFF;

    // ---- init: pack W2/W3 into per-lane mma fragments (tf32-rounded) ----
    for (int idx = tid; idx < 8 * 8 * 32; idx += THREADS) {
        int l = idx & 31, nt = (idx >> 5) & 7, ks = idx >> 8;
        int gg = l >> 2, qq = l & 3, n = nt * 8 + gg;
        uint2 v;
        v.x = f2tf(W2[(ks * 8 + qq) * 64 + n]);
        v.y = f2tf(W2[(ks * 8 + qq + 4) * 64 + n]);
        B2f[idx] = v;
    }
    for (int idx = tid; idx < 8 * 4 * 32; idx += THREADS) {
        int l = idx & 31, nt = (idx >> 5) & 3, ks = idx >> 7;
        int gg = l >> 2, qq = l & 3, n = nt * 8 + gg;
        uint2 v;
        v.x = f2tf(W3[(ks * 8 + qq) * 32 + n]);
        v.y = f2tf(W3[(ks * 8 + qq + 4) * 32 + n]);
        B3f[idx] = v;
    }
    for (int i = tid; i < 128; i += THREADS) w1s[i] = W1[i];
    for (int i = tid; i < 64;  i += THREADS) b1s[i] = b1[i];
    for (int i = tid; i < 128 * STR; i += THREADS) Atile[i] = 0.f;  // rows >=119 stay 0

    // pinned bias fragments
    float2 b2p[8], b3p[4];
    #pragma unroll
    for (int nt = 0; nt < 8; nt++) {
        int cb = nt * 8 + 2 * q;
        b2p[nt] = make_float2(b2[cb], b2[cb + 1]);
    }
    #pragma unroll
    for (int nt = 0; nt < 4; nt++) {
        int cb = nt * 8 + 2 * q;
        b3p[nt] = make_float2(b3[cb], b3[cb + 1]);
    }
    __syncthreads();

    for (int s = blockIdx.x; s < nstages; s += gridDim.x) {
        const int tok0 = s * TOKS;
        const int vtok = min(TOKS, NT - tok0);
        const int vrows = vtok * 17;

        // ---- layer 1: h1 = relu((agg x) @ W1 + b1) -> scr (x direct from gmem) ----
        if (tid < vrows) {
            int t = tid / 17, jo = tid - t * 17;
            const float2* xb = (const float2*)x + (size_t)(tok0 + t) * 17;
            float2 xa = make_float2(0.f, 0.f);
            int cnt = c_cnt[jo];
            #pragma unroll
            for (int i = 0; i < 5; i++) if (i < cnt) {
                float2 v = __ldg(xb + c_nbr[jo][i]);
                xa.x += v.x; xa.y += v.y;
            }
            const float4* w1a = (const float4*)w1s;         // W1[0][*]
            const float4* w1b = (const float4*)(w1s + 64);  // W1[1][*]
            const float4* b1v = (const float4*)b1s;
            float* sr = scr + tid * STR;
            #pragma unroll
            for (int fc = 0; fc < 16; fc++) {
                float4 wa = w1a[fc], wb = w1b[fc], bb = b1v[fc], h;
                h.x = fmaxf(xa.x * wa.x + xa.y * wb.x + bb.x, 0.f);
                h.y = fmaxf(xa.x * wa.y + xa.y * wb.y + bb.y, 0.f);
                h.z = fmaxf(xa.x * wa.z + xa.y * wb.z + bb.z, 0.f);
                h.w = fmaxf(xa.x * wa.w + xa.y * wb.w + bb.w, 0.f);
                *(float4*)(sr + fc * 4) = h;
            }
        }
        __syncthreads();

        // ---- A1 = agg(h1), tf32 -> A tile ----
        for (int task = tid; task < vrows * 16; task += THREADS) {
            int r = task >> 4, fc = task & 15;
            int t = r / 17, jo = r - t * 17, rb = t * 17;
            int cnt = c_cnt[jo];
            float4 acc = make_float4(0.f, 0.f, 0.f, 0.f);
            #pragma unroll
            for (int i = 0; i < 5; i++) if (i < cnt) {
                float4 v = *(const float4*)(scr + (rb + c_nbr[jo][i]) * STR + fc * 4);
                acc.x += v.x; acc.y += v.y; acc.z += v.z; acc.w += v.w;
            }
            uint4 o;
            o.x = f2tf(acc.x); o.y = f2tf(acc.y); o.z = f2tf(acc.z); o.w = f2tf(acc.w);
            *(uint4*)(Atile + r * STR + fc * 4) = o;
        }
        __syncthreads();

        // ---- GEMM1: C1 = A @ W2  (warp owns rows r0, r0+8; N=64) ----
        {
            float c1[8][4];
            #pragma unroll
            for (int nt = 0; nt < 8; nt++)
                #pragma unroll
                for (int i = 0; i < 4; i++) c1[nt][i] = 0.f;

            const uint32_t* arow0 = (const uint32_t*)Atile + r0 * STR;
            const uint32_t* arow1 = (const uint32_t*)Atile + (r0 + 8) * STR;
            #pragma unroll
            for (int ks = 0; ks < 8; ks++) {
                const int k0 = ks * 8;
                uint32_t a[4];
                a[0] = arow0[k0 + q];     a[1] = arow1[k0 + q];
                a[2] = arow0[k0 + q + 4]; a[3] = arow1[k0 + q + 4];
                const uint2* bf = B2f + ks * 256 + lane;
                #pragma unroll
                for (int nt = 0; nt < 8; nt++) {
                    uint2 b = bf[nt * 32];
                    mma8(c1[nt], a, b.x, b.y);
                }
            }
            __syncthreads();   // all A1 reads of scr done before overwrite
            #pragma unroll
            for (int nt = 0; nt < 8; nt++) {
                int cb = nt * 8 + 2 * q;
                float2 lo, hi;
                lo.x = fmaxf(c1[nt][0] + b2p[nt].x, 0.f);
                lo.y = fmaxf(c1[nt][1] + b2p[nt].y, 0.f);
                hi.x = fmaxf(c1[nt][2] + b2p[nt].x, 0.f);
                hi.y = fmaxf(c1[nt][3] + b2p[nt].y, 0.f);
                *(float2*)(scr + r0 * STR + cb) = lo;
                *(float2*)(scr + (r0 + 8) * STR + cb) = hi;
            }
        }
        __syncthreads();

        // ---- A2 = agg(relu(g2+b2)), tf32 -> A tile ----
        for (int task = tid; task < vrows * 16; task += THREADS) {
            int r = task >> 4, fc = task & 15;
            int t = r / 17, jo = r - t * 17, rb = t * 17;
            int cnt = c_cnt[jo];
            float4 acc = make_float4(0.f, 0.f, 0.f, 0.f);
            #pragma unroll
            for (int i = 0; i < 5; i++) if (i < cnt) {
                float4 v = *(const float4*)(scr + (rb + c_nbr[jo][i]) * STR + fc * 4);
                acc.x += v.x; acc.y += v.y; acc.z += v.z; acc.w += v.w;
            }
            uint4 o;
            o.x = f2tf(acc.x); o.y = f2tf(acc.y); o.z = f2tf(acc.z); o.w = f2tf(acc.w);
            *(uint4*)(Atile + r * STR + fc * 4) = o;
        }
        __syncthreads();

        // ---- GEMM2: out = A @ W3 + b3 (N=32), fragments straight to gmem ----
        {
            float c2[4][4];
            #pragma unroll
            for (int nt = 0; nt < 4; nt++)
                #pragma unroll
                for (int i = 0; i < 4; i++) c2[nt][i] = 0.f;

            const uint32_t* arow0 = (const uint32_t*)Atile + r0 * STR;
            const uint32_t* arow1 = (const uint32_t*)Atile + (r0 + 8) * STR;
            #pragma unroll
            for (int ks = 0; ks < 8; ks++) {
                const int k0 = ks * 8;
                uint32_t a[4];
                a[0] = arow0[k0 + q];     a[1] = arow1[k0 + q];
                a[2] = arow0[k0 + q + 4]; a[3] = arow1[k0 + q + 4];
                const uint2* bf = B3f + ks * 128 + lane;
                #pragma unroll
                for (int nt = 0; nt < 4; nt++) {
                    uint2 b = bf[nt * 32];
                    mma8(c2[nt], a, b.x, b.y);
                }
            }
            float* ob = out + (size_t)tok0 * 17 * 32;
            #pragma unroll
            for (int nt = 0; nt < 4; nt++) {
                int cb = nt * 8 + 2 * q;
                if (r0 < vrows) {
                    float2 v = make_float2(c2[nt][0] + b3p[nt].x, c2[nt][1] + b3p[nt].y);
                    *(float2*)(ob + r0 * 32 + cb) = v;
                }
                if (r0 + 8 < vrows) {
                    float2 v = make_float2(c2[nt][2] + b3p[nt].x, c2[nt][3] + b3p[nt].y);
                    *(float2*)(ob + (r0 + 8) * 32 + cb) = v;
                }
            }
        }
        __syncthreads();   // protect Atile/scr before next stage
    }
}

extern "C" void kernel_launch(void* const* d_in, const int* in_sizes, int n_in,
                              void* d_out, int out_size) {
    const float* x  = (const float*)d_in[0];
    const float* W1 = (const float*)d_in[1];
    const float* b1 = (const float*)d_in[2];
    const float* W2 = (const float*)d_in[3];
    const float* b2 = (const float*)d_in[4];
    const float* W3 = (const float*)d_in[5];
    const float* b3 = (const float*)d_in[6];
    float* out = (float*)d_out;

    const int NT = in_sizes[0] / (17 * 2);          // 65536 tokens
    const int nstages = (NT + TOKS - 1) / TOKS;     // 9363

    static int attr_done = 0;
    if (!attr_done) {
        cudaFuncSetAttribute(sge_mma, cudaFuncAttributeMaxDynamicSharedMemorySize, SMEM_BYTES);
        attr_done = 1;
    }
    int grid = nstages < 296 ? nstages : 296;
    sge_mma<<<grid, THREADS, SMEM_BYTES>>>(x, W1, b1, W2, b2, W3, b3, out, NT, nstages);
}

// round 6
// speedup vs baseline: 1.9858x; 1.4347x over previous
#include <cuda_runtime.h>
#include <cstdint>

#define TOKS 7
#define THREADS 256
#define STR 68            // float stride for A / scr tiles (conflict-free)

// smem float offsets
#define A_FOFF    0                       // 128 x STR tf32 A tile
#define SCR_FOFF  (128 * STR)             // 128 x STR f32 scratch (h2)
#define B2F_FOFF  (2 * 128 * STR)         // 8ks x 8nt x 32lane x float2 = 4096 floats
#define B3F_FOFF  (B2F_FOFF + 4096)       // 8ks x 4nt x 32lane x float2 = 2048 floats
#define XS_FOFF   (B3F_FOFF + 2048)       // 8 warps x 17 float2 = 272 floats
#define SMEM_FLOATS (XS_FOFF + 272)
#define SMEM_BYTES  (SMEM_FLOATS * 4)     // ~95.3KB -> 2 CTAs/SM

__constant__ int c_cnt[17] = {5,3,3,2,2,4,4,3,3,2,2,3,3,3,3,2,2};
__constant__ int c_nbr[17][5] = {
    {0,1,2,5,6},{1,0,3,0,0},{2,0,4,0,0},{3,1,0,0,0},{4,2,0,0,0},
    {5,0,7,11,0},{6,0,8,12,0},{7,5,9,0,0},{8,6,10,0,0},{9,7,0,0,0},
    {10,8,0,0,0},{11,5,13,0,0},{12,6,14,0,0},{13,11,15,0,0},{14,12,16,0,0},
    {15,13,0,0,0},{16,14,0,0,0}};

__device__ __forceinline__ uint32_t f2tf(float f) {
    uint32_t r; asm("cvt.rna.tf32.f32 %0, %1;" : "=r"(r) : "f"(f)); return r;
}

__device__ __forceinline__ void mma8(float c[4], const uint32_t a[4], uint32_t b0, uint32_t b1) {
    asm volatile(
        "mma.sync.aligned.m16n8k8.row.col.f32.tf32.tf32.f32 "
        "{%0,%1,%2,%3}, {%4,%5,%6,%7}, {%8,%9}, {%0,%1,%2,%3};"
        : "+f"(c[0]), "+f"(c[1]), "+f"(c[2]), "+f"(c[3])
        : "r"(a[0]), "r"(a[1]), "r"(a[2]), "r"(a[3]), "r"(b0), "r"(b1));
}

// unrolled skeleton aggregation (adj + I, all-ones)
__device__ __forceinline__ void aggF(const float* s, float* g) {
    g[0]  = s[0] + s[1] + s[2] + s[5] + s[6];
    g[1]  = s[1] + s[0] + s[3];
    g[2]  = s[2] + s[0] + s[4];
    g[3]  = s[3] + s[1];
    g[4]  = s[4] + s[2];
    g[5]  = s[5] + s[0] + s[7] + s[11];
    g[6]  = s[6] + s[0] + s[8] + s[12];
    g[7]  = s[7] + s[5] + s[9];
    g[8]  = s[8] + s[6] + s[10];
    g[9]  = s[9] + s[7];
    g[10] = s[10] + s[8];
    g[11] = s[11] + s[5] + s[13];
    g[12] = s[12] + s[6] + s[14];
    g[13] = s[13] + s[11] + s[15];
    g[14] = s[14] + s[12] + s[16];
    g[15] = s[15] + s[13];
    g[16] = s[16] + s[14];
}

extern __shared__ float sm[];

__global__ void __launch_bounds__(THREADS, 2)
sge_mma(const float* __restrict__ x,
        const float* __restrict__ W1, const float* __restrict__ b1,
        const float* __restrict__ W2, const float* __restrict__ b2,
        const float* __restrict__ W3, const float* __restrict__ b3,
        float* __restrict__ out, int NT, int nstages)
{
    const int tid = threadIdx.x;
    const int warp = tid >> 5, lane = tid & 31;
    const int g = lane >> 2, q = lane & 3;
    const int r0 = warp * 16 + g;            // this thread's MMA rows (r0, r0+8)

    float* Atile = sm + A_FOFF;              // tf32 bit patterns
    float* scr   = sm + SCR_FOFF;
    uint2* B2f   = (uint2*)(sm + B2F_FOFF);
    uint2* B3f   = (uint2*)(sm + B3F_FOFF);
    float2* xsw  = (float2*)(sm + XS_FOFF) + warp * 17;

    // ---- init: pack W2/W3 into per-lane mma fragments (tf32-rounded) ----
    for (int idx = tid; idx < 8 * 8 * 32; idx += THREADS) {
        int l = idx & 31, nt = (idx >> 5) & 7, ks = idx >> 8;
        int gg = l >> 2, qq = l & 3, n = nt * 8 + gg;
        uint2 v;
        v.x = f2tf(W2[(ks * 8 + qq) * 64 + n]);
        v.y = f2tf(W2[(ks * 8 + qq + 4) * 64 + n]);
        B2f[idx] = v;
    }
    for (int idx = tid; idx < 8 * 4 * 32; idx += THREADS) {
        int l = idx & 31, nt = (idx >> 5) & 3, ks = idx >> 7;
        int gg = l >> 2, qq = l & 3, n = nt * 8 + gg;
        uint2 v;
        v.x = f2tf(W3[(ks * 8 + qq) * 32 + n]);
        v.y = f2tf(W3[(ks * 8 + qq + 4) * 32 + n]);
        B3f[idx] = v;
    }
    for (int i = tid; i < 128 * STR; i += THREADS) Atile[i] = 0.f;  // pad rows stay 0

    // per-lane layer-1 weights/biases (registers)
    const float w1a0 = __ldg(W1 + lane),      w1a1 = __ldg(W1 + 64 + lane);
    const float w1b0 = __ldg(W1 + 32 + lane), w1b1 = __ldg(W1 + 96 + lane);
    const float b1a  = __ldg(b1 + lane),      b1b  = __ldg(b1 + 32 + lane);

    // pinned bias fragments
    float2 b2p[8], b3p[4];
    #pragma unroll
    for (int nt = 0; nt < 8; nt++) {
        int cb = nt * 8 + 2 * q;
        b2p[nt] = make_float2(b2[cb], b2[cb + 1]);
    }
    #pragma unroll
    for (int nt = 0; nt < 4; nt++) {
        int cb = nt * 8 + 2 * q;
        b3p[nt] = make_float2(b3[cb], b3[cb + 1]);
    }

    // ---- initial x prefetch (warp w owns token w of its stage) ----
    float2 xcur = make_float2(0.f, 0.f);
    {
        int t0 = blockIdx.x * TOKS + warp;
        if (warp < TOKS && lane < 17 && t0 < NT)
            xcur = __ldg((const float2*)x + (size_t)t0 * 17 + lane);
    }
    __syncthreads();

    for (int s = blockIdx.x; s < nstages; s += gridDim.x) {
        const int tok0 = s * TOKS;
        const int vtok = min(TOKS, NT - tok0);
        const int vrows = vtok * 17;

        // ---- stage current x into warp-local smem, prefetch next stage ----
        if (warp < TOKS && lane < 17) xsw[lane] = xcur;
        {
            int ns = s + gridDim.x;
            int tn = ns * TOKS + warp;
            xcur = make_float2(0.f, 0.f);
            if (warp < TOKS && lane < 17 && ns < nstages && tn < NT)
                xcur = __ldg((const float2*)x + (size_t)tn * 17 + lane);
        }
        __syncwarp();

        // ---- layer 1 + A1, fully warp-local in registers ----
        if (warp < vtok) {
            float xax[17], xay[17];
            #pragma unroll
            for (int j = 0; j < 17; j++) { float2 v = xsw[j]; xax[j] = v.x; xay[j] = v.y; }
            float gx[17], gy[17];
            aggF(xax, gx); aggF(xay, gy);

            uint32_t* au = (uint32_t*)Atile + (17 * warp) * STR;
            float h[17], ga[17];
            #pragma unroll
            for (int j = 0; j < 17; j++)
                h[j] = fmaxf(fmaf(gx[j], w1a0, fmaf(gy[j], w1a1, b1a)), 0.f);
            aggF(h, ga);
            #pragma unroll
            for (int j = 0; j < 17; j++) au[j * STR + lane] = f2tf(ga[j]);

            #pragma unroll
            for (int j = 0; j < 17; j++)
                h[j] = fmaxf(fmaf(gx[j], w1b0, fmaf(gy[j], w1b1, b1b)), 0.f);
            aggF(h, ga);
            #pragma unroll
            for (int j = 0; j < 17; j++) au[j * STR + lane + 32] = f2tf(ga[j]);
        }
        __syncthreads();   // A1 ready

        // ---- GEMM1: C1 = A @ W2 (N=64); h2 = relu(C1 + b2) -> scr ----
        {
            float c1[8][4];
            #pragma unroll
            for (int nt = 0; nt < 8; nt++)
                #pragma unroll
                for (int i = 0; i < 4; i++) c1[nt][i] = 0.f;

            const uint32_t* arow0 = (const uint32_t*)Atile + r0 * STR;
            const uint32_t* arow1 = (const uint32_t*)Atile + (r0 + 8) * STR;
            #pragma unroll
            for (int ks = 0; ks < 8; ks++) {
                const int k0 = ks * 8;
                uint32_t a[4];
                a[0] = arow0[k0 + q];     a[1] = arow1[k0 + q];
                a[2] = arow0[k0 + q + 4]; a[3] = arow1[k0 + q + 4];
                const uint2* bf = B2f + ks * 256 + lane;
                #pragma unroll
                for (int nt = 0; nt < 8; nt++) {
                    uint2 b = bf[nt * 32];
                    mma8(c1[nt], a, b.x, b.y);
                }
            }
            #pragma unroll
            for (int nt = 0; nt < 8; nt++) {
                int cb = nt * 8 + 2 * q;
                float2 lo, hi;
                lo.x = fmaxf(c1[nt][0] + b2p[nt].x, 0.f);
                lo.y = fmaxf(c1[nt][1] + b2p[nt].y, 0.f);
                hi.x = fmaxf(c1[nt][2] + b2p[nt].x, 0.f);
                hi.y = fmaxf(c1[nt][3] + b2p[nt].y, 0.f);
                *(float2*)(scr + r0 * STR + cb) = lo;
                *(float2*)(scr + (r0 + 8) * STR + cb) = hi;
            }
        }
        __syncthreads();   // h2 ready

        // ---- A2 = agg(h2), tf32 -> A tile ----
        for (int task = tid; task < vrows * 16; task += THREADS) {
            int r = task >> 4, fc = task & 15;
            int t = r / 17, jo = r - t * 17, rb = t * 17;
            int cnt = c_cnt[jo];
            float4 acc = make_float4(0.f, 0.f, 0.f, 0.f);
            #pragma unroll
            for (int i = 0; i < 5; i++) if (i < cnt) {
                float4 v = *(const float4*)(scr + (rb + c_nbr[jo][i]) * STR + fc * 4);
                acc.x += v.x; acc.y += v.y; acc.z += v.z; acc.w += v.w;
            }
            uint4 o;
            o.x = f2tf(acc.x); o.y = f2tf(acc.y); o.z = f2tf(acc.z); o.w = f2tf(acc.w);
            *(uint4*)(Atile + r * STR + fc * 4) = o;
        }
        __syncthreads();   // A2 ready

        // ---- GEMM2: out = A @ W3 + b3 (N=32), fragments straight to gmem ----
        {
            float c2[4][4];
            #pragma unroll
            for (int nt = 0; nt < 4; nt++)
                #pragma unroll
                for (int i = 0; i < 4; i++) c2[nt][i] = 0.f;

            const uint32_t* arow0 = (const uint32_t*)Atile + r0 * STR;
            const uint32_t* arow1 = (const uint32_t*)Atile + (r0 + 8) * STR;
            #pragma unroll
            for (int ks = 0; ks < 8; ks++) {
                const int k0 = ks * 8;
                uint32_t a[4];
                a[0] = arow0[k0 + q];     a[1] = arow1[k0 + q];
                a[2] = arow0[k0 + q + 4]; a[3] = arow1[k0 + q + 4];
                const uint2* bf = B3f + ks * 128 + lane;
                #pragma unroll
                for (int nt = 0; nt < 4; nt++) {
                    uint2 b = bf[nt * 32];
                    mma8(c2[nt], a, b.x, b.y);
                }
            }
            float* ob = out + (size_t)tok0 * 17 * 32;
            #pragma unroll
            for (int nt = 0; nt < 4; nt++) {
                int cb = nt * 8 + 2 * q;
                if (r0 < vrows) {
                    float2 v = make_float2(c2[nt][0] + b3p[nt].x, c2[nt][1] + b3p[nt].y);
                    *(float2*)(ob + r0 * 32 + cb) = v;
                }
                if (r0 + 8 < vrows) {
                    float2 v = make_float2(c2[nt][2] + b3p[nt].x, c2[nt][3] + b3p[nt].y);
                    *(float2*)(ob + (r0 + 8) * 32 + cb) = v;
                }
            }
        }
        __syncthreads();   // protect Atile/scr before next stage
    }
}

extern "C" void kernel_launch(void* const* d_in, const int* in_sizes, int n_in,
                              void* d_out, int out_size) {
    const float* x  = (const float*)d_in[0];
    const float* W1 = (const float*)d_in[1];
    const float* b1 = (const float*)d_in[2];
    const float* W2 = (const float*)d_in[3];
    const float* b2 = (const float*)d_in[4];
    const float* W3 = (const float*)d_in[5];
    const float* b3 = (const float*)d_in[6];
    float* out = (float*)d_out;

    const int NT = in_sizes[0] / (17 * 2);          // 65536 tokens
    const int nstages = (NT + TOKS - 1) / TOKS;     // 9363

    static int attr_done = 0;
    if (!attr_done) {
        cudaFuncSetAttribute(sge_mma, cudaFuncAttributeMaxDynamicSharedMemorySize, SMEM_BYTES);
        attr_done = 1;
    }
    int grid = nstages < 296 ? nstages : 296;
    sge_mma<<<grid, THREADS, SMEM_BYTES>>>(x, W1, b1, W2, b2, W3, b3, out, NT, nstages);
}

// round 7
// speedup vs baseline: 2.7343x; 1.3769x over previous
#include <cuda_runtime.h>
#include <cstdint>

#define TOKS 7
#define THREADS 256
#define STR 68            // float stride for A / scr tiles

// smem float offsets
#define A_FOFF    0                       // 128 x STR tf32 A tile
#define SCR_FOFF  (128 * STR)             // 128 x STR f32 scratch (h2)
#define B2F_FOFF  (2 * 128 * STR)         // 8ks x 8nt x 32lane x float2 = 4096 floats
#define B3F_FOFF  (B2F_FOFF + 4096)       // 8ks x 4nt x 32lane x float2 = 2048 floats
#define XS_FOFF   (B3F_FOFF + 2048)       // 8 warps x 17 float2 = 272 floats
#define SMEM_FLOATS (XS_FOFF + 272)
#define SMEM_BYTES  (SMEM_FLOATS * 4)     // ~95.3KB -> 2 CTAs/SM

__device__ __forceinline__ uint32_t f2tf(float f) {
    uint32_t r; asm("cvt.rna.tf32.f32 %0, %1;" : "=r"(r) : "f"(f)); return r;
}

__device__ __forceinline__ void mma8(float c[4], const uint32_t a[4], uint32_t b0, uint32_t b1) {
    asm volatile(
        "mma.sync.aligned.m16n8k8.row.col.f32.tf32.tf32.f32 "
        "{%0,%1,%2,%3}, {%4,%5,%6,%7}, {%8,%9}, {%0,%1,%2,%3};"
        : "+f"(c[0]), "+f"(c[1]), "+f"(c[2]), "+f"(c[3])
        : "r"(a[0]), "r"(a[1]), "r"(a[2]), "r"(a[3]), "r"(b0), "r"(b1));
}

// unrolled skeleton aggregation (adj + I, all-ones)
__device__ __forceinline__ void aggF(const float* s, float* g) {
    g[0]  = s[0] + s[1] + s[2] + s[5] + s[6];
    g[1]  = s[1] + s[0] + s[3];
    g[2]  = s[2] + s[0] + s[4];
    g[3]  = s[3] + s[1];
    g[4]  = s[4] + s[2];
    g[5]  = s[5] + s[0] + s[7] + s[11];
    g[6]  = s[6] + s[0] + s[8] + s[12];
    g[7]  = s[7] + s[5] + s[9];
    g[8]  = s[8] + s[6] + s[10];
    g[9]  = s[9] + s[7];
    g[10] = s[10] + s[8];
    g[11] = s[11] + s[5] + s[13];
    g[12] = s[12] + s[6] + s[14];
    g[13] = s[13] + s[11] + s[15];
    g[14] = s[14] + s[12] + s[16];
    g[15] = s[15] + s[13];
    g[16] = s[16] + s[14];
}

extern __shared__ float sm[];

__global__ void __launch_bounds__(THREADS, 2)
sge_mma(const float* __restrict__ x,
        const float* __restrict__ W1, const float* __restrict__ b1,
        const float* __restrict__ W2, const float* __restrict__ b2,
        const float* __restrict__ W3, const float* __restrict__ b3,
        float* __restrict__ out, int NT, int nstages)
{
    const int tid = threadIdx.x;
    const int warp = tid >> 5, lane = tid & 31;
    const int g = lane >> 2, q = lane & 3;
    const int r0 = warp * 16 + g;            // this thread's MMA rows (r0, r0+8)

    float* Atile = sm + A_FOFF;              // tf32 bit patterns
    float* scr   = sm + SCR_FOFF;
    uint2* B2f   = (uint2*)(sm + B2F_FOFF);
    uint2* B3f   = (uint2*)(sm + B3F_FOFF);
    float2* xsw  = (float2*)(sm + XS_FOFF) + warp * 17;

    // ---- init: pack W2/W3 into per-lane mma fragments (tf32-rounded) ----
    for (int idx = tid; idx < 8 * 8 * 32; idx += THREADS) {
        int l = idx & 31, nt = (idx >> 5) & 7, ks = idx >> 8;
        int gg = l >> 2, qq = l & 3, n = nt * 8 + gg;
        uint2 v;
        v.x = f2tf(W2[(ks * 8 + qq) * 64 + n]);
        v.y = f2tf(W2[(ks * 8 + qq + 4) * 64 + n]);
        B2f[idx] = v;
    }
    for (int idx = tid; idx < 8 * 4 * 32; idx += THREADS) {
        int l = idx & 31, nt = (idx >> 5) & 3, ks = idx >> 7;
        int gg = l >> 2, qq = l & 3, n = nt * 8 + gg;
        uint2 v;
        v.x = f2tf(W3[(ks * 8 + qq) * 32 + n]);
        v.y = f2tf(W3[(ks * 8 + qq + 4) * 32 + n]);
        B3f[idx] = v;
    }
    for (int i = tid; i < 128 * STR; i += THREADS) Atile[i] = 0.f;  // pad rows stay 0

    // per-lane layer-1 weights/biases (registers)
    const float w1a0 = __ldg(W1 + lane),      w1a1 = __ldg(W1 + 64 + lane);
    const float w1b0 = __ldg(W1 + 32 + lane), w1b1 = __ldg(W1 + 96 + lane);
    const float b1a  = __ldg(b1 + lane),      b1b  = __ldg(b1 + 32 + lane);

    // pinned bias fragments
    float2 b2p[8], b3p[4];
    #pragma unroll
    for (int nt = 0; nt < 8; nt++) {
        int cb = nt * 8 + 2 * q;
        b2p[nt] = make_float2(b2[cb], b2[cb + 1]);
    }
    #pragma unroll
    for (int nt = 0; nt < 4; nt++) {
        int cb = nt * 8 + 2 * q;
        b3p[nt] = make_float2(b3[cb], b3[cb + 1]);
    }

    // ---- initial x prefetch (warp w owns token w of its stage) ----
    float2 xcur = make_float2(0.f, 0.f);
    {
        int t0 = blockIdx.x * TOKS + warp;
        if (warp < TOKS && lane < 17 && t0 < NT)
            xcur = __ldg((const float2*)x + (size_t)t0 * 17 + lane);
    }
    __syncthreads();

    for (int s = blockIdx.x; s < nstages; s += gridDim.x) {
        const int tok0 = s * TOKS;
        const int vtok = min(TOKS, NT - tok0);
        const int vrows = vtok * 17;

        // ---- stage current x into warp-local smem, prefetch next stage ----
        if (warp < TOKS && lane < 17) xsw[lane] = xcur;
        {
            int ns = s + gridDim.x;
            int tn = ns * TOKS + warp;
            xcur = make_float2(0.f, 0.f);
            if (warp < TOKS && lane < 17 && ns < nstages && tn < NT)
                xcur = __ldg((const float2*)x + (size_t)tn * 17 + lane);
        }
        __syncwarp();

        // ---- layer 1 + A1, fully warp-local in registers ----
        if (warp < vtok) {
            float xax[17], xay[17];
            #pragma unroll
            for (int j = 0; j < 17; j++) { float2 v = xsw[j]; xax[j] = v.x; xay[j] = v.y; }
            float gx[17], gy[17];
            aggF(xax, gx); aggF(xay, gy);

            uint32_t* au = (uint32_t*)Atile + (17 * warp) * STR;
            float h[17], ga[17];
            #pragma unroll
            for (int j = 0; j < 17; j++)
                h[j] = fmaxf(fmaf(gx[j], w1a0, fmaf(gy[j], w1a1, b1a)), 0.f);
            aggF(h, ga);
            #pragma unroll
            for (int j = 0; j < 17; j++) au[j * STR + lane] = f2tf(ga[j]);

            #pragma unroll
            for (int j = 0; j < 17; j++)
                h[j] = fmaxf(fmaf(gx[j], w1b0, fmaf(gy[j], w1b1, b1b)), 0.f);
            aggF(h, ga);
            #pragma unroll
            for (int j = 0; j < 17; j++) au[j * STR + lane + 32] = f2tf(ga[j]);
        }
        __syncthreads();   // A1 ready

        // ---- GEMM1: C1 = A @ W2 (N=64); h2 = relu(C1 + b2) -> scr ----
        {
            float c1[8][4];
            #pragma unroll
            for (int nt = 0; nt < 8; nt++)
                #pragma unroll
                for (int i = 0; i < 4; i++) c1[nt][i] = 0.f;

            const uint32_t* arow0 = (const uint32_t*)Atile + r0 * STR;
            const uint32_t* arow1 = (const uint32_t*)Atile + (r0 + 8) * STR;
            #pragma unroll
            for (int ks = 0; ks < 8; ks++) {
                const int k0 = ks * 8;
                uint32_t a[4];
                a[0] = arow0[k0 + q];     a[1] = arow1[k0 + q];
                a[2] = arow0[k0 + q + 4]; a[3] = arow1[k0 + q + 4];
                const uint2* bf = B2f + ks * 256 + lane;
                #pragma unroll
                for (int nt = 0; nt < 8; nt++) {
                    uint2 b = bf[nt * 32];
                    mma8(c1[nt], a, b.x, b.y);
                }
            }
            #pragma unroll
            for (int nt = 0; nt < 8; nt++) {
                int cb = nt * 8 + 2 * q;
                float2 lo, hi;
                lo.x = fmaxf(c1[nt][0] + b2p[nt].x, 0.f);
                lo.y = fmaxf(c1[nt][1] + b2p[nt].y, 0.f);
                hi.x = fmaxf(c1[nt][2] + b2p[nt].x, 0.f);
                hi.y = fmaxf(c1[nt][3] + b2p[nt].y, 0.f);
                *(float2*)(scr + r0 * STR + cb) = lo;
                *(float2*)(scr + (r0 + 8) * STR + cb) = hi;
            }
        }
        __syncthreads();   // h2 ready

        // ---- A2 = agg(h2): column-wise, register-reuse (job = token x feat) ----
        for (int job = tid; job < vtok * 64; job += THREADS) {
            int t = job >> 6, f = job & 63;
            const float* sc = scr + (t * 17) * STR + f;
            uint32_t* au = (uint32_t*)Atile + (t * 17) * STR + f;
            float h[17];
            #pragma unroll
            for (int j = 0; j < 17; j++) h[j] = sc[j * STR];
            float ga[17];
            aggF(h, ga);
            #pragma unroll
            for (int j = 0; j < 17; j++) au[j * STR] = f2tf(ga[j]);
        }
        __syncthreads();   // A2 ready

        // ---- GEMM2: out = A @ W3 + b3 (N=32), fragments straight to gmem ----
        {
            float c2[4][4];
            #pragma unroll
            for (int nt = 0; nt < 4; nt++)
                #pragma unroll
                for (int i = 0; i < 4; i++) c2[nt][i] = 0.f;

            const uint32_t* arow0 = (const uint32_t*)Atile + r0 * STR;
            const uint32_t* arow1 = (const uint32_t*)Atile + (r0 + 8) * STR;
            #pragma unroll
            for (int ks = 0; ks < 8; ks++) {
                const int k0 = ks * 8;
                uint32_t a[4];
                a[0] = arow0[k0 + q];     a[1] = arow1[k0 + q];
                a[2] = arow0[k0 + q + 4]; a[3] = arow1[k0 + q + 4];
                const uint2* bf = B3f + ks * 128 + lane;
                #pragma unroll
                for (int nt = 0; nt < 4; nt++) {
                    uint2 b = bf[nt * 32];
                    mma8(c2[nt], a, b.x, b.y);
                }
            }
            float* ob = out + (size_t)tok0 * 17 * 32;
            #pragma unroll
            for (int nt = 0; nt < 4; nt++) {
                int cb = nt * 8 + 2 * q;
                if (r0 < vrows) {
                    float2 v = make_float2(c2[nt][0] + b3p[nt].x, c2[nt][1] + b3p[nt].y);
                    *(float2*)(ob + r0 * 32 + cb) = v;
                }
                if (r0 + 8 < vrows) {
                    float2 v = make_float2(c2[nt][2] + b3p[nt].x, c2[nt][3] + b3p[nt].y);
                    *(float2*)(ob + (r0 + 8) * 32 + cb) = v;
                }
            }
        }
        __syncthreads();   // protect Atile/scr before next stage
    }
}

extern "C" void kernel_launch(void* const* d_in, const int* in_sizes, int n_in,
                              void* d_out, int out_size) {
    const float* x  = (const float*)d_in[0];
    const float* W1 = (const float*)d_in[1];
    const float* b1 = (const float*)d_in[2];
    const float* W2 = (const float*)d_in[3];
    const float* b2 = (const float*)d_in[4];
    const float* W3 = (const float*)d_in[5];
    const float* b3 = (const float*)d_in[6];
    float* out = (float*)d_out;

    const int NT = in_sizes[0] / (17 * 2);          // 65536 tokens
    const int nstages = (NT + TOKS - 1) / TOKS;     // 9363

    static int attr_done = 0;
    if (!attr_done) {
        cudaFuncSetAttribute(sge_mma, cudaFuncAttributeMaxDynamicSharedMemorySize, SMEM_BYTES);
        attr_done = 1;
    }
    int grid = nstages < 296 ? nstages : 296;
    sge_mma<<<grid, THREADS, SMEM_BYTES>>>(x, W1, b1, W2, b2, W3, b3, out, NT, nstages);
}

// round 8
// speedup vs baseline: 3.1315x; 1.1453x over previous
#include <cuda_runtime.h>
#include <cstdint>

#define TOKS 7
#define THREADS 256
#define STR 68            // float stride for X / S tiles (conflict-free)

// smem float offsets
#define X_FOFF    0                       // 128 x STR: A1 (tf32), then Y (f32)
#define S_FOFF    (128 * STR)             // 128 x STR: h2 (tf32)
#define B2F_FOFF  (2 * 128 * STR)         // 8ks x 8nt x 32lane x float2 = 4096 floats
#define B3F_FOFF  (B2F_FOFF + 4096)       // 8ks x 4nt x 32lane x float2 = 2048 floats
#define XS_FOFF   (B3F_FOFF + 2048)       // 8 warps x 17 float2 = 272 floats
#define SMEM_FLOATS (XS_FOFF + 272)
#define SMEM_BYTES  (SMEM_FLOATS * 4)     // ~95.3KB -> 2 CTAs/SM

__device__ __forceinline__ uint32_t f2tf(float f) {
    uint32_t r; asm("cvt.rna.tf32.f32 %0, %1;" : "=r"(r) : "f"(f)); return r;
}

__device__ __forceinline__ void mma8(float c[4], const uint32_t a[4], uint32_t b0, uint32_t b1) {
    asm volatile(
        "mma.sync.aligned.m16n8k8.row.col.f32.tf32.tf32.f32 "
        "{%0,%1,%2,%3}, {%4,%5,%6,%7}, {%8,%9}, {%0,%1,%2,%3};"
        : "+f"(c[0]), "+f"(c[1]), "+f"(c[2]), "+f"(c[3])
        : "r"(a[0]), "r"(a[1]), "r"(a[2]), "r"(a[3]), "r"(b0), "r"(b1));
}

// unrolled skeleton aggregation (adj + I, all-ones)
__device__ __forceinline__ void aggF(const float* s, float* g) {
    g[0]  = s[0] + s[1] + s[2] + s[5] + s[6];
    g[1]  = s[1] + s[0] + s[3];
    g[2]  = s[2] + s[0] + s[4];
    g[3]  = s[3] + s[1];
    g[4]  = s[4] + s[2];
    g[5]  = s[5] + s[0] + s[7] + s[11];
    g[6]  = s[6] + s[0] + s[8] + s[12];
    g[7]  = s[7] + s[5] + s[9];
    g[8]  = s[8] + s[6] + s[10];
    g[9]  = s[9] + s[7];
    g[10] = s[10] + s[8];
    g[11] = s[11] + s[5] + s[13];
    g[12] = s[12] + s[6] + s[14];
    g[13] = s[13] + s[11] + s[15];
    g[14] = s[14] + s[12] + s[16];
    g[15] = s[15] + s[13];
    g[16] = s[16] + s[14];
}

extern __shared__ float sm[];

__global__ void __launch_bounds__(THREADS, 2)
sge_mma(const float* __restrict__ x,
        const float* __restrict__ W1, const float* __restrict__ b1,
        const float* __restrict__ W2, const float* __restrict__ b2,
        const float* __restrict__ W3, const float* __restrict__ b3,
        float* __restrict__ out, int NT, int nstages)
{
    const int tid = threadIdx.x;
    const int warp = tid >> 5, lane = tid & 31;
    const int g = lane >> 2, q = lane & 3;
    const int mg = warp >> 1, ng = warp & 1;   // GEMM1: 32x32 warp tile
    const int r0 = warp * 16 + g;              // GEMM2: 16x32 warp tile

    float* X = sm + X_FOFF;                    // A1 tile (tf32) / Y tile (f32)
    float* S = sm + S_FOFF;                    // h2 tile (tf32)
    uint2* B2f = (uint2*)(sm + B2F_FOFF);
    uint2* B3f = (uint2*)(sm + B3F_FOFF);
    float2* xsw = (float2*)(sm + XS_FOFF) + warp * 17;

    // ---- init: pack W2/W3 into per-lane mma fragments (tf32-rounded) ----
    for (int idx = tid; idx < 8 * 8 * 32; idx += THREADS) {
        int l = idx & 31, nt = (idx >> 5) & 7, ks = idx >> 8;
        int gg = l >> 2, qq = l & 3, n = nt * 8 + gg;
        uint2 v;
        v.x = f2tf(W2[(ks * 8 + qq) * 64 + n]);
        v.y = f2tf(W2[(ks * 8 + qq + 4) * 64 + n]);
        B2f[idx] = v;
    }
    for (int idx = tid; idx < 8 * 4 * 32; idx += THREADS) {
        int l = idx & 31, nt = (idx >> 5) & 3, ks = idx >> 7;
        int gg = l >> 2, qq = l & 3, n = nt * 8 + gg;
        uint2 v;
        v.x = f2tf(W3[(ks * 8 + qq) * 32 + n]);
        v.y = f2tf(W3[(ks * 8 + qq + 4) * 32 + n]);
        B3f[idx] = v;
    }
    for (int i = tid; i < 2 * 128 * STR; i += THREADS) sm[i] = 0.f;  // clean tiles

    // per-lane layer-1 weights/biases for features {2*lane, 2*lane+1}
    const float wA0 = __ldg(W1 + 2 * lane),     wA1 = __ldg(W1 + 64 + 2 * lane);
    const float wB0 = __ldg(W1 + 2 * lane + 1), wB1 = __ldg(W1 + 64 + 2 * lane + 1);
    const float bA  = __ldg(b1 + 2 * lane),     bB  = __ldg(b1 + 2 * lane + 1);

    // b2 fragments for this warp's N-slice
    float2 b2p[4];
    #pragma unroll
    for (int nt = 0; nt < 4; nt++) {
        int cb = (ng * 4 + nt) * 8 + 2 * q;
        b2p[nt] = make_float2(b2[cb], b2[cb + 1]);
    }

    // ---- initial x prefetch (warp w owns token w of its stage) ----
    float2 xcur = make_float2(0.f, 0.f);
    {
        int t0 = blockIdx.x * TOKS + warp;
        if (warp < TOKS && lane < 17 && t0 < NT)
            xcur = __ldg((const float2*)x + (size_t)t0 * 17 + lane);
    }
    __syncthreads();

    for (int s = blockIdx.x; s < nstages; s += gridDim.x) {
        const int tok0 = s * TOKS;
        const int vtok = min(TOKS, NT - tok0);

        // ---- stage current x, prefetch next ----
        if (warp < TOKS && lane < 17) xsw[lane] = xcur;
        {
            int ns = s + gridDim.x;
            int tn = ns * TOKS + warp;
            xcur = make_float2(0.f, 0.f);
            if (warp < TOKS && lane < 17 && ns < nstages && tn < NT)
                xcur = __ldg((const float2*)x + (size_t)tn * 17 + lane);
        }
        __syncwarp();

        // ---- layer 1 + A1 (warp-local registers) -> X as tf32 ----
        if (warp < vtok) {
            float xax[17], xay[17];
            #pragma unroll
            for (int j = 0; j < 17; j++) { float2 v = xsw[j]; xax[j] = v.x; xay[j] = v.y; }
            float gx[17], gy[17];
            aggF(xax, gx); aggF(xay, gy);

            float h[17], ga[17], gb[17];
            #pragma unroll
            for (int j = 0; j < 17; j++)
                h[j] = fmaxf(fmaf(gx[j], wA0, fmaf(gy[j], wA1, bA)), 0.f);
            aggF(h, ga);
            #pragma unroll
            for (int j = 0; j < 17; j++)
                h[j] = fmaxf(fmaf(gx[j], wB0, fmaf(gy[j], wB1, bB)), 0.f);
            aggF(h, gb);

            uint32_t* au = (uint32_t*)X + (17 * warp) * STR + 2 * lane;
            #pragma unroll
            for (int j = 0; j < 17; j++) {
                uint2 v; v.x = f2tf(ga[j]); v.y = f2tf(gb[j]);
                *(uint2*)(au + j * STR) = v;
            }
        }
        __syncthreads();   // A1 ready

        // ---- GEMM1 (32x32 tiles): h2 = relu(A1@W2 + b2) -> S as tf32 ----
        {
            float c1[2][4][4];
            #pragma unroll
            for (int mt = 0; mt < 2; mt++)
                #pragma unroll
                for (int nt = 0; nt < 4; nt++)
                    #pragma unroll
                    for (int i = 0; i < 4; i++) c1[mt][nt][i] = 0.f;

            const uint32_t* am0 = (const uint32_t*)X + (mg * 32 + g) * STR;
            const uint32_t* am1 = am0 + 16 * STR;
            #pragma unroll
            for (int ks = 0; ks < 8; ks++) {
                const int k0 = ks * 8;
                uint32_t a0[4], a1[4];
                a0[0] = am0[k0 + q];           a0[1] = am0[8 * STR + k0 + q];
                a0[2] = am0[k0 + q + 4];       a0[3] = am0[8 * STR + k0 + q + 4];
                a1[0] = am1[k0 + q];           a1[1] = am1[8 * STR + k0 + q];
                a1[2] = am1[k0 + q + 4];       a1[3] = am1[8 * STR + k0 + q + 4];
                const uint2* bf = B2f + ks * 256 + ng * 128 + lane;
                #pragma unroll
                for (int nt = 0; nt < 4; nt++) {
                    uint2 b = bf[nt * 32];
                    mma8(c1[0][nt], a0, b.x, b.y);
                    mma8(c1[1][nt], a1, b.x, b.y);
                }
            }
            uint32_t* su = (uint32_t*)S;
            #pragma unroll
            for (int mt = 0; mt < 2; mt++) {
                int r = mg * 32 + mt * 16 + g;
                #pragma unroll
                for (int nt = 0; nt < 4; nt++) {
                    int cb = (ng * 4 + nt) * 8 + 2 * q;
                    uint2 lo, hi;
                    lo.x = f2tf(fmaxf(c1[mt][nt][0] + b2p[nt].x, 0.f));
                    lo.y = f2tf(fmaxf(c1[mt][nt][1] + b2p[nt].y, 0.f));
                    hi.x = f2tf(fmaxf(c1[mt][nt][2] + b2p[nt].x, 0.f));
                    hi.y = f2tf(fmaxf(c1[mt][nt][3] + b2p[nt].y, 0.f));
                    *(uint2*)(su + r * STR + cb) = lo;
                    *(uint2*)(su + (r + 8) * STR + cb) = hi;
                }
            }
        }
        __syncthreads();   // h2 ready

        // ---- GEMM2 (16x32 tiles): Y = h2 @ W3 -> X (f32) ----
        {
            float c2[4][4];
            #pragma unroll
            for (int nt = 0; nt < 4; nt++)
                #pragma unroll
                for (int i = 0; i < 4; i++) c2[nt][i] = 0.f;

            const uint32_t* arow0 = (const uint32_t*)S + r0 * STR;
            const uint32_t* arow1 = arow0 + 8 * STR;
            #pragma unroll
            for (int ks = 0; ks < 8; ks++) {
                const int k0 = ks * 8;
                uint32_t a[4];
                a[0] = arow0[k0 + q];     a[1] = arow1[k0 + q];
                a[2] = arow0[k0 + q + 4]; a[3] = arow1[k0 + q + 4];
                const uint2* bf = B3f + ks * 128 + lane;
                #pragma unroll
                for (int nt = 0; nt < 4; nt++) {
                    uint2 b = bf[nt * 32];
                    mma8(c2[nt], a, b.x, b.y);
                }
            }
            #pragma unroll
            for (int nt = 0; nt < 4; nt++) {
                int cb = nt * 8 + 2 * q;
                *(float2*)(X + r0 * STR + cb) = make_float2(c2[nt][0], c2[nt][1]);
                *(float2*)(X + (r0 + 8) * STR + cb) = make_float2(c2[nt][2], c2[nt][3]);
            }
        }
        __syncthreads();   // Y ready

        // ---- out = agg(Y) + b3, straight to gmem (warp = one token) ----
        for (int job = tid; job < vtok * 32; job += THREADS) {
            int t = job >> 5, f = job & 31;
            const float* yc = X + (t * 17) * STR + f;
            float y[17];
            #pragma unroll
            for (int j = 0; j < 17; j++) y[j] = yc[j * STR];
            float o[17];
            aggF(y, o);
            float bb = __ldg(b3 + f);
            float* ob = out + ((size_t)(tok0 + t) * 17) * 32 + f;
            #pragma unroll
            for (int j = 0; j < 17; j++) ob[j * 32] = o[j] + bb;
        }
        __syncthreads();   // protect X/S before next stage
    }
}

extern "C" void kernel_launch(void* const* d_in, const int* in_sizes, int n_in,
                              void* d_out, int out_size) {
    const float* x  = (const float*)d_in[0];
    const float* W1 = (const float*)d_in[1];
    const float* b1 = (const float*)d_in[2];
    const float* W2 = (const float*)d_in[3];
    const float* b2 = (const float*)d_in[4];
    const float* W3 = (const float*)d_in[5];
    const float* b3 = (const float*)d_in[6];
    float* out = (float*)d_out;

    const int NT = in_sizes[0] / (17 * 2);          // 65536 tokens
    const int nstages = (NT + TOKS - 1) / TOKS;     // 9363

    static int attr_done = 0;
    if (!attr_done) {
        cudaFuncSetAttribute(sge_mma, cudaFuncAttributeMaxDynamicSharedMemorySize, SMEM_BYTES);
        attr_done = 1;
    }
    int grid = nstages < 296 ? nstages : 296;
    sge_mma<<<grid, THREADS, SMEM_BYTES>>>(x, W1, b1, W2, b2, W3, b3, out, NT, nstages);
}

// round 10
// speedup vs baseline: 4.8449x; 1.5472x over previous
#include <cuda_runtime.h>
#include <cuda_fp16.h>
#include <cstdint>

#define TOKS 7
#define THREADS 256
#define HSTR 72           // half stride for T0/T1 rows (144B, conflict-free)
#define YSTR 68           // float stride for Yf

// smem byte offsets
#define T0_OFF   0                  // 128 x HSTR half  (A1 tile)     18432
#define T1_OFF   18432              // 128 x HSTR half  (h2 tile)     18432
#define YF_OFF   36864              // 128 x YSTR float (Y tile)      34816
#define B2F_OFF  71680              // 4ks x 8nt x 32 x uint2 = 8192
#define B3F_OFF  79872              // 4ks x 4nt x 32 x uint2 = 4096
#define XS_OFF   83968              // 8 warps x 17 float2 = 1088
#define SMEM_BYTES 85056            // -> 2 CTAs/SM

__device__ __forceinline__ void mma16(float c[4], const uint32_t a[4], uint32_t b0, uint32_t b1) {
    asm volatile(
        "mma.sync.aligned.m16n8k16.row.col.f32.f16.f16.f32 "
        "{%0,%1,%2,%3}, {%4,%5,%6,%7}, {%8,%9}, {%0,%1,%2,%3};"
        : "+f"(c[0]), "+f"(c[1]), "+f"(c[2]), "+f"(c[3])
        : "r"(a[0]), "r"(a[1]), "r"(a[2]), "r"(a[3]), "r"(b0), "r"(b1));
}

__device__ __forceinline__ uint32_t h2pack(float a, float b) {
    __half2 h = __floats2half2_rn(a, b);
    return *(uint32_t*)&h;
}

// unrolled skeleton aggregation (adj + I, all-ones)
__device__ __forceinline__ void aggF(const float* s, float* g) {
    g[0]  = s[0] + s[1] + s[2] + s[5] + s[6];
    g[1]  = s[1] + s[0] + s[3];
    g[2]  = s[2] + s[0] + s[4];
    g[3]  = s[3] + s[1];
    g[4]  = s[4] + s[2];
    g[5]  = s[5] + s[0] + s[7] + s[11];
    g[6]  = s[6] + s[0] + s[8] + s[12];
    g[7]  = s[7] + s[5] + s[9];
    g[8]  = s[8] + s[6] + s[10];
    g[9]  = s[9] + s[7];
    g[10] = s[10] + s[8];
    g[11] = s[11] + s[5] + s[13];
    g[12] = s[12] + s[6] + s[14];
    g[13] = s[13] + s[11] + s[15];
    g[14] = s[14] + s[12] + s[16];
    g[15] = s[15] + s[13];
    g[16] = s[16] + s[14];
}

extern __shared__ char smem[];

__global__ void __launch_bounds__(THREADS, 2)
sge_h(const float* __restrict__ x,
      const float* __restrict__ W1, const float* __restrict__ b1,
      const float* __restrict__ W2, const float* __restrict__ b2,
      const float* __restrict__ W3, const float* __restrict__ b3,
      float* __restrict__ out, int NT, int nstages)
{
    const int tid = threadIdx.x;
    const int warp = tid >> 5, lane = tid & 31;
    const int g = lane >> 2, q = lane & 3;
    const int mg = warp >> 1, ng = warp & 1;   // GEMM1: 32x32 warp tile
    const int r0 = warp * 16 + g;              // GEMM2: 16x32 warp tile

    __half* T0 = (__half*)(smem + T0_OFF);
    __half* T1 = (__half*)(smem + T1_OFF);
    float*  Yf = (float*)(smem + YF_OFF);
    uint2*  B2f = (uint2*)(smem + B2F_OFF);
    uint2*  B3f = (uint2*)(smem + B3F_OFF);
    float2* xsw = (float2*)(smem + XS_OFF) + warp * 17;

    // ---- init: pack W2/W3 into per-lane m16n8k16 fp16 B fragments ----
    // B2f[ks][nt][lane]: n = nt*8+g ; b0 = W2[k0+2q..+1][n], b1 = W2[k0+8+2q..+1][n]
    for (int idx = tid; idx < 4 * 8 * 32; idx += THREADS) {
        int l = idx & 31, nt = (idx >> 5) & 7, ks = idx >> 8;
        int gg = l >> 2, qq = l & 3, n = nt * 8 + gg, k0 = ks * 16 + 2 * qq;
        uint2 v;
        v.x = h2pack(W2[k0 * 64 + n],       W2[(k0 + 1) * 64 + n]);
        v.y = h2pack(W2[(k0 + 8) * 64 + n], W2[(k0 + 9) * 64 + n]);
        B2f[idx] = v;
    }
    for (int idx = tid; idx < 4 * 4 * 32; idx += THREADS) {
        int l = idx & 31, nt = (idx >> 5) & 3, ks = idx >> 7;
        int gg = l >> 2, qq = l & 3, n = nt * 8 + gg, k0 = ks * 16 + 2 * qq;
        uint2 v;
        v.x = h2pack(W3[k0 * 32 + n],       W3[(k0 + 1) * 32 + n]);
        v.y = h2pack(W3[(k0 + 8) * 32 + n], W3[(k0 + 9) * 32 + n]);
        B3f[idx] = v;
    }
    for (int i = tid; i < (2 * 128 * HSTR) / 2; i += THREADS)
        ((uint32_t*)T0)[i] = 0u;   // zero T0+T1 (contiguous), pad rows stay 0

    // per-lane layer-1 weights/biases for features {2*lane, 2*lane+1}
    const float wA0 = __ldg(W1 + 2 * lane),     wA1 = __ldg(W1 + 64 + 2 * lane);
    const float wB0 = __ldg(W1 + 2 * lane + 1), wB1 = __ldg(W1 + 64 + 2 * lane + 1);
    const float bA  = __ldg(b1 + 2 * lane),     bB  = __ldg(b1 + 2 * lane + 1);
    const float b3r = __ldg(b3 + lane);

    // b2 fragments for this warp's GEMM1 N-slice
    float2 b2p[4];
    #pragma unroll
    for (int nt = 0; nt < 4; nt++) {
        int cb = (ng * 4 + nt) * 8 + 2 * q;
        b2p[nt] = make_float2(b2[cb], b2[cb + 1]);
    }

    // ---- initial x prefetch (warp w owns token w of its stage) ----
    float2 xcur = make_float2(0.f, 0.f);
    {
        int t0 = blockIdx.x * TOKS + warp;
        if (warp < TOKS && lane < 17 && t0 < NT)
            xcur = __ldg((const float2*)x + (size_t)t0 * 17 + lane);
    }
    __syncthreads();

    int ptok0 = 0, pvtok = 0;   // previous stage pending Y

    for (int s = blockIdx.x; s < nstages; s += gridDim.x) {
        const int tok0 = s * TOKS;
        const int vtok = min(TOKS, NT - tok0);

        // ---- stage x, prefetch next ----
        if (warp < TOKS && lane < 17) xsw[lane] = xcur;
        {
            int ns = s + gridDim.x;
            int tn = ns * TOKS + warp;
            xcur = make_float2(0.f, 0.f);
            if (warp < TOKS && lane < 17 && ns < nstages && tn < NT)
                xcur = __ldg((const float2*)x + (size_t)tn * 17 + lane);
        }
        __syncwarp();

        // ---- phase 1a: layer 1 + A1 (warp-local) -> T0 (fp16) ----
        if (warp < vtok) {
            float xax[17], xay[17];
            #pragma unroll
            for (int j = 0; j < 17; j++) { float2 v = xsw[j]; xax[j] = v.x; xay[j] = v.y; }
            float gx[17], gy[17];
            aggF(xax, gx); aggF(xay, gy);

            float h[17], ga[17], gb[17];
            #pragma unroll
            for (int j = 0; j < 17; j++)
                h[j] = fmaxf(fmaf(gx[j], wA0, fmaf(gy[j], wA1, bA)), 0.f);
            aggF(h, ga);
            #pragma unroll
            for (int j = 0; j < 17; j++)
                h[j] = fmaxf(fmaf(gx[j], wB0, fmaf(gy[j], wB1, bB)), 0.f);
            aggF(h, gb);

            uint32_t* au = (uint32_t*)(T0 + (17 * warp) * HSTR + 2 * lane);
            #pragma unroll
            for (int j = 0; j < 17; j++)
                au[j * (HSTR / 2)] = h2pack(ga[j], gb[j]);
        }

        // ---- phase 1b: out = agg(prev Y) + b3 -> gmem ----
        if (warp < pvtok) {
            const float* yc = Yf + (warp * 17) * YSTR + lane;
            float y[17];
            #pragma unroll
            for (int j = 0; j < 17; j++) y[j] = yc[j * YSTR];
            float o[17];
            aggF(y, o);
            float* ob = out + ((size_t)(ptok0 + warp) * 17) * 32 + lane;
            #pragma unroll
            for (int j = 0; j < 17; j++) ob[j * 32] = o[j] + b3r;
        }
        __syncthreads();   // A1 ready, prev Y consumed

        // ---- GEMM1 (32x32 tiles, fp16 k16): h2 = relu(A1@W2 + b2) -> T1 ----
        {
            float c1[2][4][4];
            #pragma unroll
            for (int mt = 0; mt < 2; mt++)
                #pragma unroll
                for (int nt = 0; nt < 4; nt++)
                    #pragma unroll
                    for (int i = 0; i < 4; i++) c1[mt][nt][i] = 0.f;

            const __half* am0 = T0 + (mg * 32 + g) * HSTR;
            const __half* am1 = am0 + 16 * HSTR;
            #pragma unroll
            for (int ks = 0; ks < 4; ks++) {
                const int k0 = ks * 16 + 2 * q;
                uint32_t a0[4], a1[4];
                a0[0] = *(const uint32_t*)(am0 + k0);
                a0[1] = *(const uint32_t*)(am0 + 8 * HSTR + k0);
                a0[2] = *(const uint32_t*)(am0 + k0 + 8);
                a0[3] = *(const uint32_t*)(am0 + 8 * HSTR + k0 + 8);
                a1[0] = *(const uint32_t*)(am1 + k0);
                a1[1] = *(const uint32_t*)(am1 + 8 * HSTR + k0);
                a1[2] = *(const uint32_t*)(am1 + k0 + 8);
                a1[3] = *(const uint32_t*)(am1 + 8 * HSTR + k0 + 8);
                const uint2* bf = B2f + ks * 256 + ng * 128 + lane;
                #pragma unroll
                for (int nt = 0; nt < 4; nt++) {
                    uint2 b = bf[nt * 32];
                    mma16(c1[0][nt], a0, b.x, b.y);
                    mma16(c1[1][nt], a1, b.x, b.y);
                }
            }
            #pragma unroll
            for (int mt = 0; mt < 2; mt++) {
                int r = mg * 32 + mt * 16 + g;
                #pragma unroll
                for (int nt = 0; nt < 4; nt++) {
                    int cb = (ng * 4 + nt) * 8 + 2 * q;
                    *(uint32_t*)(T1 + r * HSTR + cb) =
                        h2pack(fmaxf(c1[mt][nt][0] + b2p[nt].x, 0.f),
                               fmaxf(c1[mt][nt][1] + b2p[nt].y, 0.f));
                    *(uint32_t*)(T1 + (r + 8) * HSTR + cb) =
                        h2pack(fmaxf(c1[mt][nt][2] + b2p[nt].x, 0.f),
                               fmaxf(c1[mt][nt][3] + b2p[nt].y, 0.f));
                }
            }
        }
        __syncthreads();   // h2 ready

        // ---- GEMM2 (16x32 tiles, fp16 k16): Y = h2 @ W3 -> Yf (f32) ----
        {
            float c2[4][4];
            #pragma unroll
            for (int nt = 0; nt < 4; nt++)
                #pragma unroll
                for (int i = 0; i < 4; i++) c2[nt][i] = 0.f;

            const __half* ar = T1 + r0 * HSTR;
            #pragma unroll
            for (int ks = 0; ks < 4; ks++) {
                const int k0 = ks * 16 + 2 * q;
                uint32_t a[4];
                a[0] = *(const uint32_t*)(ar + k0);
                a[1] = *(const uint32_t*)(ar + 8 * HSTR + k0);
                a[2] = *(const uint32_t*)(ar + k0 + 8);
                a[3] = *(const uint32_t*)(ar + 8 * HSTR + k0 + 8);
                const uint2* bf = B3f + ks * 128 + lane;
                #pragma unroll
                for (int nt = 0; nt < 4; nt++) {
                    uint2 b = bf[nt * 32];
                    mma16(c2[nt], a, b.x, b.y);
                }
            }
            #pragma unroll
            for (int nt = 0; nt < 4; nt++) {
                int cb = nt * 8 + 2 * q;
                *(float2*)(Yf + r0 * YSTR + cb) = make_float2(c2[nt][0], c2[nt][1]);
                *(float2*)(Yf + (r0 + 8) * YSTR + cb) = make_float2(c2[nt][2], c2[nt][3]);
            }
        }
        ptok0 = tok0; pvtok = vtok;
        __syncthreads();   // Y ready for next phase 1b
    }

    // ---- tail: flush last stage's Y ----
    if (warp < pvtok) {
        const float* yc = Yf + (warp * 17) * YSTR + lane;
        float y[17];
        #pragma unroll
        for (int j = 0; j < 17; j++) y[j] = yc[j * YSTR];
        float o[17];
        aggF(y, o);
        float* ob = out + ((size_t)(ptok0 + warp) * 17) * 32 + lane;
        #pragma unroll
        for (int j = 0; j < 17; j++) ob[j * 32] = o[j] + b3r;
    }
}

extern "C" void kernel_launch(void* const* d_in, const int* in_sizes, int n_in,
                              void* d_out, int out_size) {
    const float* x  = (const float*)d_in[0];
    const float* W1 = (const float*)d_in[1];
    const float* b1 = (const float*)d_in[2];
    const float* W2 = (const float*)d_in[3];
    const float* b2 = (const float*)d_in[4];
    const float* W3 = (const float*)d_in[5];
    const float* b3 = (const float*)d_in[6];
    float* out = (float*)d_out;

    const int NT = in_sizes[0] / (17 * 2);          // 65536 tokens
    const int nstages = (NT + TOKS - 1) / TOKS;     // 9363

    static int attr_done = 0;
    if (!attr_done) {
        cudaFuncSetAttribute(sge_h, cudaFuncAttributeMaxDynamicSharedMemorySize, SMEM_BYTES);
        attr_done = 1;
    }
    int grid = nstages < 296 ? nstages : 296;
    sge_h<<<grid, THREADS, SMEM_BYTES>>>(x, W1, b1, W2, b2, W3, b3, out, NT, nstages);
}

// round 11
// speedup vs baseline: 5.5437x; 1.1442x over previous
#include <cuda_runtime.h>
#include <cuda_fp16.h>
#include <cstdint>

#define TOKS 7
#define THREADS 256
#define HSTR 72           // half stride for T0 rows (144B, conflict-free)
#define YSTR 68           // float stride for Yf

// smem byte offsets
#define T0_OFF   0                  // 128 x HSTR half  (A1 tile)   18432
#define YF_OFF   18432              // 128 x YSTR float (Y tile)    34816
#define B2F_OFF  53248              // 4ks x 8nt x 32 x uint2 = 8192
#define B3F_OFF  61440              // 4ks x 4nt x 32 x uint2 = 4096
#define XS_OFF   65536              // 8 warps x 17 float2 = 1088
#define SMEM_BYTES 66624            // -> 2 CTAs/SM

__device__ __forceinline__ void mma16(float c[4], const uint32_t a[4], uint32_t b0, uint32_t b1) {
    asm volatile(
        "mma.sync.aligned.m16n8k16.row.col.f32.f16.f16.f32 "
        "{%0,%1,%2,%3}, {%4,%5,%6,%7}, {%8,%9}, {%0,%1,%2,%3};"
        : "+f"(c[0]), "+f"(c[1]), "+f"(c[2]), "+f"(c[3])
        : "r"(a[0]), "r"(a[1]), "r"(a[2]), "r"(a[3]), "r"(b0), "r"(b1));
}

__device__ __forceinline__ uint32_t h2pack(float a, float b) {
    __half2 h = __floats2half2_rn(a, b);
    return *(uint32_t*)&h;
}

// unrolled skeleton aggregation (adj + I, all-ones)
__device__ __forceinline__ void aggF(const float* s, float* g) {
    g[0]  = s[0] + s[1] + s[2] + s[5] + s[6];
    g[1]  = s[1] + s[0] + s[3];
    g[2]  = s[2] + s[0] + s[4];
    g[3]  = s[3] + s[1];
    g[4]  = s[4] + s[2];
    g[5]  = s[5] + s[0] + s[7] + s[11];
    g[6]  = s[6] + s[0] + s[8] + s[12];
    g[7]  = s[7] + s[5] + s[9];
    g[8]  = s[8] + s[6] + s[10];
    g[9]  = s[9] + s[7];
    g[10] = s[10] + s[8];
    g[11] = s[11] + s[5] + s[13];
    g[12] = s[12] + s[6] + s[14];
    g[13] = s[13] + s[11] + s[15];
    g[14] = s[14] + s[12] + s[16];
    g[15] = s[15] + s[13];
    g[16] = s[16] + s[14];
}

extern __shared__ char smem[];

__global__ void __launch_bounds__(THREADS, 2)
sge_h(const float* __restrict__ x,
      const float* __restrict__ W1, const float* __restrict__ b1,
      const float* __restrict__ W2, const float* __restrict__ b2,
      const float* __restrict__ W3, const float* __restrict__ b3,
      float* __restrict__ out, int NT, int nstages)
{
    const int tid = threadIdx.x;
    const int warp = tid >> 5, lane = tid & 31;
    const int g = lane >> 2, q = lane & 3;
    const int r0 = warp * 16 + g;              // warp tile rows (r0, r0+8)

    __half* T0 = (__half*)(smem + T0_OFF);
    float*  Yf = (float*)(smem + YF_OFF);
    uint2*  B2f = (uint2*)(smem + B2F_OFF);
    uint2*  B3f = (uint2*)(smem + B3F_OFF);
    float2* xsw = (float2*)(smem + XS_OFF) + warp * 17;

    // ---- init: pack W2/W3 into per-lane m16n8k16 fp16 B fragments ----
    for (int idx = tid; idx < 4 * 8 * 32; idx += THREADS) {
        int l = idx & 31, nt = (idx >> 5) & 7, ks = idx >> 8;
        int gg = l >> 2, qq = l & 3, n = nt * 8 + gg, k0 = ks * 16 + 2 * qq;
        uint2 v;
        v.x = h2pack(W2[k0 * 64 + n],       W2[(k0 + 1) * 64 + n]);
        v.y = h2pack(W2[(k0 + 8) * 64 + n], W2[(k0 + 9) * 64 + n]);
        B2f[idx] = v;
    }
    for (int idx = tid; idx < 4 * 4 * 32; idx += THREADS) {
        int l = idx & 31, nt = (idx >> 5) & 3, ks = idx >> 7;
        int gg = l >> 2, qq = l & 3, n = nt * 8 + gg, k0 = ks * 16 + 2 * qq;
        uint2 v;
        v.x = h2pack(W3[k0 * 32 + n],       W3[(k0 + 1) * 32 + n]);
        v.y = h2pack(W3[(k0 + 8) * 32 + n], W3[(k0 + 9) * 32 + n]);
        B3f[idx] = v;
    }
    for (int i = tid; i < (128 * HSTR) / 2; i += THREADS)
        ((uint32_t*)T0)[i] = 0u;   // zero T0, pad rows 119..127 stay 0

    // per-lane layer-1 weights/biases for features {2*lane, 2*lane+1}
    const float wA0 = __ldg(W1 + 2 * lane),     wA1 = __ldg(W1 + 64 + 2 * lane);
    const float wB0 = __ldg(W1 + 2 * lane + 1), wB1 = __ldg(W1 + 64 + 2 * lane + 1);
    const float bA  = __ldg(b1 + 2 * lane),     bB  = __ldg(b1 + 2 * lane + 1);
    const float b3r = __ldg(b3 + lane);

    // b2 fragments: warp covers all 64 N cols
    float2 b2p[8];
    #pragma unroll
    for (int nt = 0; nt < 8; nt++) {
        int cb = nt * 8 + 2 * q;
        b2p[nt] = make_float2(b2[cb], b2[cb + 1]);
    }

    // ---- initial x prefetch (warp w owns token w of its stage) ----
    float2 xcur = make_float2(0.f, 0.f);
    {
        int t0 = blockIdx.x * TOKS + warp;
        if (warp < TOKS && lane < 17 && t0 < NT)
            xcur = __ldg((const float2*)x + (size_t)t0 * 17 + lane);
    }
    __syncthreads();

    int ptok0 = 0, pvtok = 0;   // previous stage pending Y

    for (int s = blockIdx.x; s < nstages; s += gridDim.x) {
        const int tok0 = s * TOKS;
        const int vtok = min(TOKS, NT - tok0);

        // ---- stage x, prefetch next ----
        if (warp < TOKS && lane < 17) xsw[lane] = xcur;
        {
            int ns = s + gridDim.x;
            int tn = ns * TOKS + warp;
            xcur = make_float2(0.f, 0.f);
            if (warp < TOKS && lane < 17 && ns < nstages && tn < NT)
                xcur = __ldg((const float2*)x + (size_t)tn * 17 + lane);
        }
        __syncwarp();

        // ---- phase A1: layer 1 + agg (warp-local) -> T0 (fp16) ----
        if (warp < vtok) {
            float xax[17], xay[17];
            #pragma unroll
            for (int j = 0; j < 17; j++) { float2 v = xsw[j]; xax[j] = v.x; xay[j] = v.y; }
            float gx[17], gy[17];
            aggF(xax, gx); aggF(xay, gy);

            float h[17], ga[17], gb[17];
            #pragma unroll
            for (int j = 0; j < 17; j++)
                h[j] = fmaxf(fmaf(gx[j], wA0, fmaf(gy[j], wA1, bA)), 0.f);
            aggF(h, ga);
            #pragma unroll
            for (int j = 0; j < 17; j++)
                h[j] = fmaxf(fmaf(gx[j], wB0, fmaf(gy[j], wB1, bB)), 0.f);
            aggF(h, gb);

            uint32_t* au = (uint32_t*)(T0 + (17 * warp) * HSTR + 2 * lane);
            #pragma unroll
            for (int j = 0; j < 17; j++)
                au[j * (HSTR / 2)] = h2pack(ga[j], gb[j]);
        }

        // ---- phase A2: out = agg(prev Y) + b3 -> gmem ----
        if (warp < pvtok) {
            const float* yc = Yf + (warp * 17) * YSTR + lane;
            float y[17];
            #pragma unroll
            for (int j = 0; j < 17; j++) y[j] = yc[j * YSTR];
            float o[17];
            aggF(y, o);
            float* ob = out + ((size_t)(ptok0 + warp) * 17) * 32 + lane;
            #pragma unroll
            for (int j = 0; j < 17; j++) ob[j * 32] = o[j] + b3r;
        }
        __syncthreads();   // T0 ready, prev Y consumed

        // ---- phase B: GEMM1 (16x64) -> regs -> GEMM2 (16x32) -> Yf ----
        {
            // GEMM1: c1[nt] over N=64, rows r0,r0+8
            float c1[8][4];
            #pragma unroll
            for (int nt = 0; nt < 8; nt++)
                #pragma unroll
                for (int i = 0; i < 4; i++) c1[nt][i] = 0.f;

            const __half* ar = T0 + r0 * HSTR;
            #pragma unroll
            for (int ks = 0; ks < 4; ks++) {
                const int k0 = ks * 16 + 2 * q;
                uint32_t a[4];
                a[0] = *(const uint32_t*)(ar + k0);
                a[1] = *(const uint32_t*)(ar + 8 * HSTR + k0);
                a[2] = *(const uint32_t*)(ar + k0 + 8);
                a[3] = *(const uint32_t*)(ar + 8 * HSTR + k0 + 8);
                const uint2* bf = B2f + ks * 256 + lane;
                #pragma unroll
                for (int nt = 0; nt < 8; nt++) {
                    uint2 b = bf[nt * 32];
                    mma16(c1[nt], a, b.x, b.y);
                }
            }

            // bias + relu + pack: C-frags (2 adjacent n8 tiles) == A-frag of one k16 tile
            uint32_t a2[4][4];
            #pragma unroll
            for (int kt = 0; kt < 4; kt++) {
                const float2 blo = b2p[2 * kt], bhi = b2p[2 * kt + 1];
                a2[kt][0] = h2pack(fmaxf(c1[2 * kt][0] + blo.x, 0.f),
                                   fmaxf(c1[2 * kt][1] + blo.y, 0.f));
                a2[kt][1] = h2pack(fmaxf(c1[2 * kt][2] + blo.x, 0.f),
                                   fmaxf(c1[2 * kt][3] + blo.y, 0.f));
                a2[kt][2] = h2pack(fmaxf(c1[2 * kt + 1][0] + bhi.x, 0.f),
                                   fmaxf(c1[2 * kt + 1][1] + bhi.y, 0.f));
                a2[kt][3] = h2pack(fmaxf(c1[2 * kt + 1][2] + bhi.x, 0.f),
                                   fmaxf(c1[2 * kt + 1][3] + bhi.y, 0.f));
            }

            // GEMM2: Y = h2 @ W3 (N=32), A-frags straight from registers
            float c2[4][4];
            #pragma unroll
            for (int nt = 0; nt < 4; nt++)
                #pragma unroll
                for (int i = 0; i < 4; i++) c2[nt][i] = 0.f;

            #pragma unroll
            for (int kt = 0; kt < 4; kt++) {
                const uint2* bf = B3f + kt * 128 + lane;
                #pragma unroll
                for (int nt = 0; nt < 4; nt++) {
                    uint2 b = bf[nt * 32];
                    mma16(c2[nt], a2[kt], b.x, b.y);
                }
            }
            #pragma unroll
            for (int nt = 0; nt < 4; nt++) {
                int cb = nt * 8 + 2 * q;
                *(float2*)(Yf + r0 * YSTR + cb) = make_float2(c2[nt][0], c2[nt][1]);
                *(float2*)(Yf + (r0 + 8) * YSTR + cb) = make_float2(c2[nt][2], c2[nt][3]);
            }
        }
        ptok0 = tok0; pvtok = vtok;
        __syncthreads();   // Y ready; T0 free for next stage
    }

    // ---- tail: flush last stage's Y ----
    if (warp < pvtok) {
        const float* yc = Yf + (warp * 17) * YSTR + lane;
        float y[17];
        #pragma unroll
        for (int j = 0; j < 17; j++) y[j] = yc[j * YSTR];
        float o[17];
        aggF(y, o);
        float* ob = out + ((size_t)(ptok0 + warp) * 17) * 32 + lane;
        #pragma unroll
        for (int j = 0; j < 17; j++) ob[j * 32] = o[j] + b3r;
    }
}

extern "C" void kernel_launch(void* const* d_in, const int* in_sizes, int n_in,
                              void* d_out, int out_size) {
    const float* x  = (const float*)d_in[0];
    const float* W1 = (const float*)d_in[1];
    const float* b1 = (const float*)d_in[2];
    const float* W2 = (const float*)d_in[3];
    const float* b2 = (const float*)d_in[4];
    const float* W3 = (const float*)d_in[5];
    const float* b3 = (const float*)d_in[6];
    float* out = (float*)d_out;

    const int NT = in_sizes[0] / (17 * 2);          // 65536 tokens
    const int nstages = (NT + TOKS - 1) / TOKS;     // 9363

    static int attr_done = 0;
    if (!attr_done) {
        cudaFuncSetAttribute(sge_h, cudaFuncAttributeMaxDynamicSharedMemorySize, SMEM_BYTES);
        attr_done = 1;
    }
    int grid = nstages < 296 ? nstages : 296;
    sge_h<<<grid, THREADS, SMEM_BYTES>>>(x, W1, b1, W2, b2, W3, b3, out, NT, nstages);
}